// round 2
// baseline (speedup 1.0000x reference)
#include <cuda_runtime.h>
#include <math.h>

// Shapes (fixed by the problem)
#define BATCH 4
#define CIN   16
#define HID   16      // hidden channels; COUT = 32 = 2*HID
#define TT    32
#define HH    128
#define WW    128
#define HWPIX (HH*WW)            // 16384
#define PLANE ((size_t)TT*HWPIX) // per (b,c): 524288
#define NOUT  ((size_t)BATCH*HID*TT*HWPIX)  // 33554432

// Scratch for Z (tanh half) and F (sigmoid half): 2 x 134 MB device globals.
__device__ float g_Z[BATCH*HID*TT*HWPIX];
__device__ float g_F[BATCH*HID*TT*HWPIX];

// ---------------------------------------------------------------------------
// Kernel A: Conv3d(16->32, k=3, pad=1) + bias + activation, split into two
// oc-halves (half 0 -> Z = tanh, half 1 -> F = sigmoid).
//
// Block: 16x16 threads, 32x32 HW tile, 4 output pixels per thread:
//   rows  h0 + 2*ty + {0,1}
//   cols  w0 + tx + {0,16}      (coalesced stores: adjacent tx -> adjacent w)
// Each thread: 4 pixels x 16 oc = 64 fp32 accumulators.
// Weight LDS.128 loads are shared across the 4 pixels -> FMA-bound inner loop.
// ---------------------------------------------------------------------------
__global__ __launch_bounds__(256) void conv_kernel(
    const float* __restrict__ x,     // [4][16][32][128][128]
    const float* __restrict__ wgt,   // [32][16][3][3][3]  (OIDHW)
    const float* __restrict__ bias)  // [32]
{
    __shared__ float ws[CIN * 27 * 16];  // [ci][tap][ocl], 27648 B
    __shared__ float xs[34][34];         // 32x32 tile + halo, 4624 B

    const int bz   = blockIdx.z;
    const int half = bz >> 7;        // 0: Z channels (oc 0..15), 1: F (oc 16..31)
    const int bt   = bz & 127;
    const int b    = bt >> 5;
    const int t    = bt & 31;
    const int h0   = blockIdx.y * 32;
    const int w0   = blockIdx.x * 32;
    const int tx   = threadIdx.x;
    const int ty   = threadIdx.y;
    const int tid  = ty * 16 + tx;

    // Stage this half's weights into smem, reordered as [ci][tap][ocl]
    // so the inner loop can do broadcast LDS.128 over ocl.
    for (int i = tid; i < CIN * 27 * 16; i += 256) {
        int ocl  = i & 15;
        int rest = i >> 4;
        int tap  = rest % 27;
        int ci   = rest / 27;
        ws[i] = wgt[(((half << 4) + ocl) * CIN + ci) * 27 + tap];
    }

    // acc[p][ocl]: p = py*2 + px  (py: row 0/1, px: col-group 0/1)
    float acc[4][16];
    #pragma unroll
    for (int p = 0; p < 4; p++)
        #pragma unroll
        for (int i = 0; i < 16; i++) acc[p][i] = 0.f;

    __syncthreads();

    for (int ci = 0; ci < CIN; ci++) {
        #pragma unroll
        for (int dt = 0; dt < 3; dt++) {
            const int tin = t + dt - 1;
            if (tin < 0 || tin >= TT) continue;   // uniform across block
            const float* src = x + ((size_t)(b * CIN + ci) * TT + tin) * HWPIX;

            __syncthreads();   // protect xs from previous slice's readers
            // Fill 34x34 halo tile (1156 elems, ~4.5 per thread)
            for (int i = tid; i < 34 * 34; i += 256) {
                int yy = i / 34, xx = i % 34;
                int hh = h0 + yy - 1, ww = w0 + xx - 1;
                float v = 0.f;
                if (hh >= 0 && hh < HH && ww >= 0 && ww < WW) v = src[hh * WW + ww];
                xs[yy][xx] = v;
            }
            __syncthreads();

            const float* wrow = &ws[(ci * 27 + dt * 9) * 16];
            #pragma unroll
            for (int ky = 0; ky < 3; ky++) {
                #pragma unroll
                for (int kx = 0; kx < 3; kx++) {
                    // 4 input values for this tap (compiler CSEs across taps)
                    float xk[4];
                    xk[0] = xs[2 * ty + 0 + ky][tx + 0  + kx];
                    xk[1] = xs[2 * ty + 0 + ky][tx + 16 + kx];
                    xk[2] = xs[2 * ty + 1 + ky][tx + 0  + kx];
                    xk[3] = xs[2 * ty + 1 + ky][tx + 16 + kx];

                    const float4* w4 =
                        reinterpret_cast<const float4*>(wrow + (ky * 3 + kx) * 16);
                    #pragma unroll
                    for (int q = 0; q < 4; q++) {
                        const float4 wv = w4[q];
                        #pragma unroll
                        for (int p = 0; p < 4; p++) {
                            acc[p][q * 4 + 0] += xk[p] * wv.x;
                            acc[p][q * 4 + 1] += xk[p] * wv.y;
                            acc[p][q * 4 + 2] += xk[p] * wv.z;
                            acc[p][q * 4 + 3] += xk[p] * wv.w;
                        }
                    }
                }
            }
        }
    }

    // Epilogue: bias + activation, write Z or F scratch. Stores coalesced
    // (adjacent tx -> adjacent w).
    float* dst = half ? g_F : g_Z;
    #pragma unroll
    for (int ocl = 0; ocl < 16; ocl++) {
        const float bv = bias[(half << 4) + ocl];
        const size_t chan = ((size_t)(b * HID + ocl) * TT + t) * HWPIX;
        #pragma unroll
        for (int p = 0; p < 4; p++) {
            const int hh = h0 + 2 * ty + (p >> 1);
            const int ww = w0 + tx + ((p & 1) << 4);
            float gate = acc[p][ocl] + bv;
            float v;
            if (half == 0) v = tanhf(gate);
            else           v = 1.f / (1.f + expf(-gate));
            dst[chan + (size_t)hh * WW + ww] = v;
        }
    }
}

// ---------------------------------------------------------------------------
// Kernel B: bidirectional fo_pool + hs, fully in registers.
// One thread per (b, c, h, w). Loads 32 (Z,F) pairs along T, computes
//   g[t]   = (1-f[t])*z[t]              -> out2 (hs)
//   hl[t]  = f[t]*hl[t-1] + g[t]        (forward)
//   hr[t]  = f[t]*hr[t+1] + g[t]        (reverse)
//   out1[t] = hl[t] + hr[t]
// ---------------------------------------------------------------------------
__global__ __launch_bounds__(256) void scan_kernel(float* __restrict__ out)
{
    const int idx = blockIdx.x * 256 + threadIdx.x;  // 0 .. B*HID*HW-1
    const int pix = idx & (HWPIX - 1);
    const int bc  = idx >> 14;                        // HWPIX = 2^14
    const size_t base = (size_t)bc * PLANE + pix;

    float f[TT], g[TT], hl[TT];
    #pragma unroll
    for (int t = 0; t < TT; t++) {
        float z  = g_Z[base + (size_t)t * HWPIX];
        float fv = g_F[base + (size_t)t * HWPIX];
        float gv = (1.f - fv) * z;
        f[t] = fv;
        g[t] = gv;
        out[NOUT + base + (size_t)t * HWPIX] = gv;   // hs
    }

    float h = 0.f;
    #pragma unroll
    for (int t = 0; t < TT; t++) { h = f[t] * h + g[t]; hl[t] = h; }

    h = 0.f;
    #pragma unroll
    for (int t = TT - 1; t >= 0; t--) {
        h = f[t] * h + g[t];
        out[base + (size_t)t * HWPIX] = hl[t] + h;   // hsl + hsr
    }
}

// ---------------------------------------------------------------------------
extern "C" void kernel_launch(void* const* d_in, const int* in_sizes, int n_in,
                              void* d_out, int out_size)
{
    const float* x    = (const float*)d_in[0];  // inputs [4,16,32,128,128]
    const float* wgt  = (const float*)d_in[1];  // conv_w [32,16,3,3,3]
    const float* bias = (const float*)d_in[2];  // conv_b [32]
    float* out = (float*)d_out;                 // [2 * 4*16*32*128*128]

    dim3 cgrid(WW / 32, HH / 32, BATCH * TT * 2);  // (4, 4, 256)
    dim3 cblock(16, 16, 1);
    conv_kernel<<<cgrid, cblock>>>(x, wgt, bias);

    const int nthreads = BATCH * HID * HWPIX;      // 1,048,576
    scan_kernel<<<nthreads / 256, 256>>>(out);
}

// round 4
// speedup vs baseline: 1.0729x; 1.0729x over previous
#include <cuda_runtime.h>
#include <math.h>

// Shapes (fixed by the problem)
#define BATCH 4
#define CIN   16
#define HID   16      // hidden channels; COUT = 32 = 2*HID
#define TT    32
#define HH    128
#define WW    128
#define HWPIX (HH*WW)            // 16384
#define PLANE ((size_t)TT*HWPIX) // per (b,c): 524288
#define NOUT  ((size_t)BATCH*HID*TT*HWPIX)  // 33554432

// Scratch for Z (tanh half) and F (sigmoid half): 2 x 134 MB device globals.
__device__ float g_Z[BATCH*HID*TT*HWPIX];
__device__ float g_F[BATCH*HID*TT*HWPIX];

// ---------------------------------------------------------------------------
// Packed fp32x2 helpers (sm_100+). fma.rn.f32x2 does 2 IEEE fp32 FMAs per
// instruction at the same issue rate as one FFMA -> 2x fp32 throughput.
// ptxas never generates it from C++; explicit PTX required.
// ---------------------------------------------------------------------------
__device__ __forceinline__ unsigned long long pack2_dup(float v) {
    unsigned long long r;
    asm("mov.b64 %0, {%1, %1};" : "=l"(r) : "f"(v));
    return r;
}
__device__ __forceinline__ unsigned long long fma2(unsigned long long a,
                                                   unsigned long long b,
                                                   unsigned long long c) {
    unsigned long long d;
    asm("fma.rn.f32x2 %0, %1, %2, %3;" : "=l"(d) : "l"(a), "l"(b), "l"(c));
    return d;
}
__device__ __forceinline__ void unpack2(unsigned long long v, float& lo, float& hi) {
    asm("mov.b64 {%0, %1}, %2;" : "=f"(lo), "=f"(hi) : "l"(v));
}

// ---------------------------------------------------------------------------
// Kernel A: Conv3d(16->32, k=3, pad=1) + bias + activation, split into two
// oc-halves (half 0 -> Z = tanh, half 1 -> F = sigmoid).
//
// Block: 16x16 threads, 32x32 HW tile, 4 output pixels per thread:
//   rows  h0 + 2*ty + {0,1}
//   cols  w0 + tx + {0,16}      (coalesced stores: adjacent tx -> adjacent w)
// Each thread: 4 pixels x 8 packed oc-pairs = 32 b64 accumulators (64 regs).
// Inner loop is fma.rn.f32x2 -> FFMA2-pipe bound at ~half the FFMA cycles.
// ---------------------------------------------------------------------------
__global__ __launch_bounds__(256) void conv_kernel(
    const float* __restrict__ x,     // [4][16][32][128][128]
    const float* __restrict__ wgt,   // [32][16][3][3][3]  (OIDHW)
    const float* __restrict__ bias)  // [32]
{
    __shared__ __align__(16) float ws[CIN * 27 * 16];  // [ci][tap][ocl], 27648 B
    __shared__ __align__(16) float xs[34][34];         // 32x32 tile + halo

    const int bz   = blockIdx.z;
    const int half = bz >> 7;        // 0: Z channels (oc 0..15), 1: F (oc 16..31)
    const int bt   = bz & 127;
    const int b    = bt >> 5;
    const int t    = bt & 31;
    const int h0   = blockIdx.y * 32;
    const int w0   = blockIdx.x * 32;
    const int tx   = threadIdx.x;
    const int ty   = threadIdx.y;
    const int tid  = ty * 16 + tx;

    // Stage this half's weights into smem, reordered as [ci][tap][ocl]
    // so the inner loop can do broadcast LDS.128 over ocl (as packed pairs).
    for (int i = tid; i < CIN * 27 * 16; i += 256) {
        int ocl  = i & 15;
        int rest = i >> 4;
        int tap  = rest % 27;
        int ci   = rest / 27;
        ws[i] = wgt[(((half << 4) + ocl) * CIN + ci) * 27 + tap];
    }

    // acc2[p][j]: p = py*2 + px; j = oc-pair (oc 2j, 2j+1)
    unsigned long long acc2[4][8];
    #pragma unroll
    for (int p = 0; p < 4; p++)
        #pragma unroll
        for (int j = 0; j < 8; j++) acc2[p][j] = 0ull;

    __syncthreads();

    for (int ci = 0; ci < CIN; ci++) {
        #pragma unroll
        for (int dt = 0; dt < 3; dt++) {
            const int tin = t + dt - 1;
            if (tin < 0 || tin >= TT) continue;   // uniform across block
            const float* src = x + ((size_t)(b * CIN + ci) * TT + tin) * HWPIX;

            __syncthreads();   // protect xs from previous slice's readers
            // Fill 34x34 halo tile (1156 elems, ~4.5 per thread)
            for (int i = tid; i < 34 * 34; i += 256) {
                int yy = i / 34, xx = i % 34;
                int hh = h0 + yy - 1, ww = w0 + xx - 1;
                float v = 0.f;
                if (hh >= 0 && hh < HH && ww >= 0 && ww < WW) v = src[hh * WW + ww];
                xs[yy][xx] = v;
            }
            __syncthreads();

            const float* wrow = &ws[(ci * 27 + dt * 9) * 16];
            #pragma unroll
            for (int ky = 0; ky < 3; ky++) {
                #pragma unroll
                for (int kx = 0; kx < 3; kx++) {
                    // 4 packed input broadcasts for this tap (CSE'd across taps)
                    unsigned long long xk2[4];
                    xk2[0] = pack2_dup(xs[2 * ty + 0 + ky][tx + 0  + kx]);
                    xk2[1] = pack2_dup(xs[2 * ty + 0 + ky][tx + 16 + kx]);
                    xk2[2] = pack2_dup(xs[2 * ty + 1 + ky][tx + 0  + kx]);
                    xk2[3] = pack2_dup(xs[2 * ty + 1 + ky][tx + 16 + kx]);

                    // 16 oc = 8 packed pairs = 4 x LDS.128
                    const ulonglong2* w2 = reinterpret_cast<const ulonglong2*>(
                        wrow + (ky * 3 + kx) * 16);
                    #pragma unroll
                    for (int q = 0; q < 4; q++) {
                        const ulonglong2 wv = w2[q];
                        #pragma unroll
                        for (int p = 0; p < 4; p++) {
                            acc2[p][2 * q + 0] = fma2(xk2[p], wv.x, acc2[p][2 * q + 0]);
                            acc2[p][2 * q + 1] = fma2(xk2[p], wv.y, acc2[p][2 * q + 1]);
                        }
                    }
                }
            }
        }
    }

    // Epilogue: bias + activation, write Z or F scratch. Stores coalesced
    // (adjacent tx -> adjacent w).
    float* dst = half ? g_F : g_Z;
    #pragma unroll
    for (int j = 0; j < 8; j++) {
        const float bv0 = bias[(half << 4) + 2 * j + 0];
        const float bv1 = bias[(half << 4) + 2 * j + 1];
        const size_t chan0 = ((size_t)(b * HID + 2 * j + 0) * TT + t) * HWPIX;
        const size_t chan1 = ((size_t)(b * HID + 2 * j + 1) * TT + t) * HWPIX;
        #pragma unroll
        for (int p = 0; p < 4; p++) {
            const int hh = h0 + 2 * ty + (p >> 1);
            const int ww = w0 + tx + ((p & 1) << 4);
            const size_t pix = (size_t)hh * WW + ww;
            float a0, a1;
            unpack2(acc2[p][j], a0, a1);
            float g0 = a0 + bv0;
            float g1 = a1 + bv1;
            float v0, v1;
            if (half == 0) {
                v0 = tanhf(g0);
                v1 = tanhf(g1);
            } else {
                v0 = 1.f / (1.f + expf(-g0));
                v1 = 1.f / (1.f + expf(-g1));
            }
            dst[chan0 + pix] = v0;
            dst[chan1 + pix] = v1;
        }
    }
}

// ---------------------------------------------------------------------------
// Kernel B: bidirectional fo_pool + hs, fully in registers.
// One thread per (b, c, h, w). Loads 32 (Z,F) pairs along T, computes
//   g[t]   = (1-f[t])*z[t]              -> out2 (hs)
//   hl[t]  = f[t]*hl[t-1] + g[t]        (forward)
//   hr[t]  = f[t]*hr[t+1] + g[t]        (reverse)
//   out1[t] = hl[t] + hr[t]
// 75% DRAM in ncu -> at the memory roofline; unchanged.
// ---------------------------------------------------------------------------
__global__ __launch_bounds__(256) void scan_kernel(float* __restrict__ out)
{
    const int idx = blockIdx.x * 256 + threadIdx.x;  // 0 .. B*HID*HW-1
    const int pix = idx & (HWPIX - 1);
    const int bc  = idx >> 14;                        // HWPIX = 2^14
    const size_t base = (size_t)bc * PLANE + pix;

    float f[TT], g[TT], hl[TT];
    #pragma unroll
    for (int t = 0; t < TT; t++) {
        float z  = g_Z[base + (size_t)t * HWPIX];
        float fv = g_F[base + (size_t)t * HWPIX];
        float gv = (1.f - fv) * z;
        f[t] = fv;
        g[t] = gv;
        out[NOUT + base + (size_t)t * HWPIX] = gv;   // hs
    }

    float h = 0.f;
    #pragma unroll
    for (int t = 0; t < TT; t++) { h = f[t] * h + g[t]; hl[t] = h; }

    h = 0.f;
    #pragma unroll
    for (int t = TT - 1; t >= 0; t--) {
        h = f[t] * h + g[t];
        out[base + (size_t)t * HWPIX] = hl[t] + h;   // hsl + hsr
    }
}

// ---------------------------------------------------------------------------
extern "C" void kernel_launch(void* const* d_in, const int* in_sizes, int n_in,
                              void* d_out, int out_size)
{
    const float* x    = (const float*)d_in[0];  // inputs [4,16,32,128,128]
    const float* wgt  = (const float*)d_in[1];  // conv_w [32,16,3,3,3]
    const float* bias = (const float*)d_in[2];  // conv_b [32]
    float* out = (float*)d_out;                 // [2 * 4*16*32*128*128]

    dim3 cgrid(WW / 32, HH / 32, BATCH * TT * 2);  // (4, 4, 256)
    dim3 cblock(16, 16, 1);
    conv_kernel<<<cgrid, cblock>>>(x, wgt, bias);

    const int nthreads = BATCH * HID * HWPIX;      // 1,048,576
    scan_kernel<<<nthreads / 256, 256>>>(out);
}